// round 6
// baseline (speedup 1.0000x reference)
#include <cuda_runtime.h>
#include <cuda_bf16.h>

#define NNODES 20000
#define NEDGES 160000
#define NB 16
#define NL 2048
#define NF 1024
#define ND 128
#define NDESC 80
#define SLOPE 0.01f

// ---- conv-branch SIMT GEMM tile ----
#define BM 128
#define BN 128
#define BK 32
#define AS 36
#define BS 132
#define SMEM_FLOATS (2*(BM*AS) + 2*(BK*BS))
#define SMEM_BYTES  (SMEM_FLOATS*4)

// ---- bf16 GCN GEMM (mma.sync) ----
#define FBK 32
#define FSA 40
#define FB_SMEM (2*2*(128*FSA)*2)

#define EBLK ((NEDGES+255)/256)
#define NBLK ((NNODES+255)/256)

// ------------------------- scratch -------------------------
__device__ __nv_bfloat16 g_xh[2][(size_t)NNODES*NF];
__device__ __nv_bfloat16 g_aggh[2][(size_t)NNODES*NF];
__device__ __nv_bfloat16 g_Wth[2][(size_t)NF*NF];
__device__ int      g_cnt[2][NNODES];
__device__ int      g_rowptr[2][NNODES+1];
__device__ int      g_cursor[2][NNODES];
__device__ int      g_srcS[2][NEDGES];
__device__ float    g_normS[2][NEDGES];
__device__ float    g_dinv[2][NNODES];
__device__ float    g_psum[2][NB*NF];
__device__ int      g_bcnt[2][NB];
__device__ unsigned g_maxenc[4][NB*ND];
__device__ float    g_fcout[2][NB*ND];

__device__ __forceinline__ float leaky(float v){ return v > 0.f ? v : SLOPE*v; }
__device__ __forceinline__ unsigned f2tf(float f){
    unsigned r; asm("cvt.rna.tf32.f32 %0,%1;" : "=r"(r) : "f"(f)); return r;
}

// ------------------------- init -------------------------
__global__ void k_init(){
    int i = blockIdx.x*256 + threadIdx.x;
    if (i < 2*NNODES) { (&g_cnt[0][0])[i] = 0; return; }
    int j = i - 2*NNODES;
    if (j < 2*NB) { (&g_bcnt[0][0])[j] = 0; return; }
    int k = j - 2*NB;
    if (k < 2*NB*NF) { (&g_psum[0][0])[k] = 0.f; return; }
    int m = k - 2*NB*NF;
    if (m < 4*NB*ND) { (&g_maxenc[0][0])[m] = 0x007FFFFFu; }
}

// ------------------------- per-branch preprocessing -------------------------
// x -> bf16
__global__ void k_xcvt(const float* __restrict__ x, int br){
    size_t i = ((size_t)blockIdx.x*256 + threadIdx.x);
    float4 v = ((const float4*)x)[i];
    __nv_bfloat162 lo = __floats2bfloat162_rn(v.x, v.y);
    __nv_bfloat162 hi = __floats2bfloat162_rn(v.z, v.w);
    uint2 pk; pk.x = *(unsigned*)&lo; pk.y = *(unsigned*)&hi;
    ((uint2*)g_xh[br])[i] = pk;
}

// blocks: [0,EBLK) edge hist | [.., +NBLK) batch counts | [.., +1024) W transpose->bf16
__global__ void k_pre(const int* __restrict__ ei, const int* __restrict__ ba,
                      const float* __restrict__ W, int br){
    int blk = blockIdx.x, t = threadIdx.x;
    if (blk < EBLK){
        int e = blk*256 + t;
        if (e < NEDGES) atomicAdd(&g_cnt[br][ei[NEDGES + e]], 1);
        return;
    }
    blk -= EBLK;
    if (blk < NBLK){
        int i = blk*256 + t;
        if (i < NNODES) atomicAdd(&g_bcnt[br][ba[i]], 1);
        return;
    }
    blk -= NBLK;
    {   // transpose W[k][n] -> Wt[n][k] (bf16), 32x32 tiles
        int bx = blk & 31, by = blk >> 5;
        __shared__ float tl[32][33];
        int tx = t & 31, ty = t >> 5;
        for (int i = ty; i < 32; i += 8)
            tl[i][tx] = W[(size_t)(by*32 + i)*NF + bx*32 + tx];
        __syncthreads();
        for (int i = ty; i < 32; i += 8)
            g_Wth[br][(size_t)(bx*32 + i)*NF + by*32 + tx] = __float2bfloat16_rn(tl[tx][i]);
    }
}

// dinv + exclusive scan, one block
__global__ void k_scan(int br){
    __shared__ int ss[1024];
    int t = threadIdx.x;
    for (int i = t; i < NNODES; i += 1024)
        g_dinv[br][i] = rsqrtf((float)(g_cnt[br][i] + 1));
    const int per = (NNODES + 1023) / 1024;
    int base = t * per;
    int s = 0;
    for (int i = 0; i < per; i++){ int idx = base + i; if (idx < NNODES) s += g_cnt[br][idx]; }
    ss[t] = s; __syncthreads();
    for (int off = 1; off < 1024; off <<= 1){
        int v = (t >= off) ? ss[t - off] : 0;
        __syncthreads();
        ss[t] += v;
        __syncthreads();
    }
    int run = ss[t] - s;
    for (int i = 0; i < per; i++){
        int idx = base + i;
        if (idx < NNODES){
            g_rowptr[br][idx] = run; g_cursor[br][idx] = run;
            run += g_cnt[br][idx];
        }
    }
    if (t == 1023) g_rowptr[br][NNODES] = ss[1023];
}

__global__ void k_scatter(const int* __restrict__ ei, int br){
    int e = blockIdx.x*256 + threadIdx.x;
    if (e < NEDGES){
        int s = ei[e], d = ei[NEDGES + e];
        int p = atomicAdd(&g_cursor[br][d], 1);
        g_srcS[br][p]  = s;
        g_normS[br][p] = g_dinv[br][s] * g_dinv[br][d];
    }
}

// agg[d] = sum_e norm*xh[src] + dinv^2*xh[d]  (bf16 in, fp32 acc, bf16 out)
__global__ void k_agg(int br){
    int d = blockIdx.x, t = threadIdx.x;       // 256 thr x 4 feats
    const uint2* x2 = (const uint2*)g_xh[br];
    float dv = g_dinv[br][d];
    float w0 = dv * dv;
    uint2 pv = x2[(size_t)d*256 + t];
    __nv_bfloat162 l0 = *(__nv_bfloat162*)&pv.x;
    __nv_bfloat162 h0 = *(__nv_bfloat162*)&pv.y;
    float a0 = __bfloat162float(l0.x)*w0, a1 = __bfloat162float(l0.y)*w0;
    float a2 = __bfloat162float(h0.x)*w0, a3 = __bfloat162float(h0.y)*w0;
    int e0 = g_rowptr[br][d], e1 = g_rowptr[br][d+1];
    for (int e = e0; e < e1; e++){
        int s = g_srcS[br][e];
        float w = g_normS[br][e];
        uint2 u = x2[(size_t)s*256 + t];
        __nv_bfloat162 lu = *(__nv_bfloat162*)&u.x;
        __nv_bfloat162 hu = *(__nv_bfloat162*)&u.y;
        a0 += __bfloat162float(lu.x)*w; a1 += __bfloat162float(lu.y)*w;
        a2 += __bfloat162float(hu.x)*w; a3 += __bfloat162float(hu.y)*w;
    }
    __nv_bfloat162 lo = __floats2bfloat162_rn(a0, a1);
    __nv_bfloat162 hi = __floats2bfloat162_rn(a2, a3);
    uint2 pk; pk.x = *(unsigned*)&lo; pk.y = *(unsigned*)&hi;
    ((uint2*)g_aggh[br])[(size_t)d*256 + t] = pk;
}

// ------------------------- PTX helpers -------------------------
__device__ __forceinline__ void cp16(void* sdst, const void* gsrc){
    unsigned s = (unsigned)__cvta_generic_to_shared(sdst);
    asm volatile("cp.async.cg.shared.global [%0],[%1],16;" :: "r"(s), "l"(gsrc));
}
__device__ __forceinline__ void cp16p(float* sdst, const float* gsrc, int nsrc){
    unsigned s = (unsigned)__cvta_generic_to_shared(sdst);
    asm volatile("cp.async.cg.shared.global [%0],[%1],16,%2;" :: "r"(s), "l"(gsrc), "r"(nsrc));
}
__device__ __forceinline__ void mma16(float* c, const unsigned* a, const unsigned* b){
    asm volatile("mma.sync.aligned.m16n8k16.row.col.f32.bf16.bf16.f32 "
        "{%0,%1,%2,%3},{%4,%5,%6,%7},{%8,%9},{%0,%1,%2,%3};"
        : "+f"(c[0]), "+f"(c[1]), "+f"(c[2]), "+f"(c[3])
        : "r"(a[0]), "r"(a[1]), "r"(a[2]), "r"(a[3]), "r"(b[0]), "r"(b[1]));
}
__device__ __forceinline__ void mma8(float* c, const unsigned* a, const unsigned* b){
    asm volatile("mma.sync.aligned.m16n8k8.row.col.f32.tf32.tf32.f32 "
        "{%0,%1,%2,%3},{%4,%5,%6,%7},{%8,%9},{%0,%1,%2,%3};"
        : "+f"(c[0]), "+f"(c[1]), "+f"(c[2]), "+f"(c[3])
        : "r"(a[0]), "r"(a[1]), "r"(a[2]), "r"(a[3]), "r"(b[0]), "r"(b[1]));
}

// ------------------------- GCN GEMM: bf16 mma.sync + pooled epilogue -------------------------
__global__ __launch_bounds__(256,2) void k_gcn(
    const __nv_bfloat16* __restrict__ Ah, const __nv_bfloat16* __restrict__ Bh,
    const float* __restrict__ bias, const int* __restrict__ batch, int M, int br)
{
    extern __shared__ char fbsm[];
    __nv_bfloat16* sA = (__nv_bfloat16*)fbsm;
    __nv_bfloat16* sB = (__nv_bfloat16*)fbsm + 2*(128*FSA);
    int t = threadIdx.x;
    int colTile = blockIdx.x*BN, rowTile = blockIdx.y*BM;
    const int KT = NF / FBK;

    auto issue = [&](int kt, int buf){
        int kbase = kt*FBK;
        __nv_bfloat16* a_s = sA + buf*(128*FSA);
        __nv_bfloat16* b_s = sB + buf*(128*FSA);
        #pragma unroll
        for (int i = 0; i < 2; i++){
            int idx = t + i*256;
            int r = idx >> 2, c = (idx & 3)*8;
            int row = rowTile + r; if (row > M-1) row = M-1;
            cp16(a_s + r*FSA + c, Ah + (size_t)row*NF + kbase + c);
        }
        #pragma unroll
        for (int i = 0; i < 2; i++){
            int idx = t + i*256;
            int r = idx >> 2, c = (idx & 3)*8;
            cp16(b_s + r*FSA + c, Bh + (size_t)(colTile + r)*NF + kbase + c);
        }
        asm volatile("cp.async.commit_group;");
    };

    int lane = t & 31, warp = t >> 5;
    int wm = warp & 1, wn = warp >> 1;
    int gid = lane >> 2, tig = lane & 3;

    float acc[4][4][4];
    #pragma unroll
    for (int a = 0; a < 4; a++)
        #pragma unroll
        for (int b = 0; b < 4; b++)
            #pragma unroll
            for (int c = 0; c < 4; c++) acc[a][b][c] = 0.f;

    issue(0, 0);
    for (int kt = 0; kt < KT; kt++){
        if (kt + 1 < KT){
            issue(kt + 1, (kt + 1) & 1);
            asm volatile("cp.async.wait_group 1;");
        } else {
            asm volatile("cp.async.wait_group 0;");
        }
        __syncthreads();
        const unsigned* aw = (const unsigned*)(sA + (kt & 1)*(128*FSA)) + (wm*64)*20;
        const unsigned* bw = (const unsigned*)(sB + (kt & 1)*(128*FSA)) + (wn*32)*20;
        #pragma unroll
        for (int ks = 0; ks < 2; ks++){
            int kb = ks*8;
            unsigned af[4][4], bfr[4][2];
            #pragma unroll
            for (int mi = 0; mi < 4; mi++){
                const unsigned* ap = aw + (mi*16 + gid)*20 + kb + tig;
                af[mi][0] = ap[0];
                af[mi][1] = ap[8*20];
                af[mi][2] = ap[4];
                af[mi][3] = ap[8*20 + 4];
            }
            #pragma unroll
            for (int ni = 0; ni < 4; ni++){
                const unsigned* bp = bw + (ni*8 + gid)*20 + kb + tig;
                bfr[ni][0] = bp[0];
                bfr[ni][1] = bp[4];
            }
            #pragma unroll
            for (int mi = 0; mi < 4; mi++)
                #pragma unroll
                for (int ni = 0; ni < 4; ni++)
                    mma16(acc[mi][ni], af[mi], bfr[ni]);
        }
        __syncthreads();
    }

    int rowBase = rowTile + wm*64;
    int colBase = colTile + wn*32;
    int garr[8];
    #pragma unroll
    for (int ri = 0; ri < 8; ri++){
        int r = rowBase + (ri >> 1)*16 + gid + (ri & 1)*8;
        garr[ri] = (r < M) ? batch[r] : -1;
    }
    #pragma unroll
    for (int ci = 0; ci < 8; ci++){
        int ni = ci >> 1;
        int col = colBase + ni*8 + tig*2 + (ci & 1);
        float bb = bias[col];
        float accv = 0.f; int gcur = -1;
        #pragma unroll
        for (int ri = 0; ri < 8; ri++){
            int g = garr[ri];
            if (g >= 0){
                float v = leaky(acc[ri >> 1][ni][(ri & 1)*2 + (ci & 1)] + bb);
                if (g != gcur){
                    if (gcur >= 0) atomicAdd(&g_psum[br][gcur*NF + col], accv);
                    gcur = g; accv = 0.f;
                }
                accv += v;
            }
        }
        if (gcur >= 0) atomicAdd(&g_psum[br][gcur*NF + col], accv);
    }
}

// ------------------------- conv-branch tf32 GEMM (max epilogue) -------------------------
__global__ __launch_bounds__(256,2) void k_gemm_max(
    const float* __restrict__ A, const float* __restrict__ B,
    int M, int K, int Nn, int br, int rowsPerGraph)
{
    extern __shared__ float sm[];
    float* sA = sm;
    float* sB = sm + 2*BM*AS;
    int t = threadIdx.x;
    int KT = (K + BK - 1) / BK;
    int rowTile = blockIdx.x*BM, colTile = blockIdx.y*BN;

    auto issue = [&](int kt, int buf){
        int kbase = kt*BK;
        float* a_s = sA + buf*(BM*AS);
        #pragma unroll
        for (int i = 0; i < 4; i++){
            int idx = t + i*256;
            int r = idx >> 3, c4 = (idx & 7)*4;
            int row = rowTile + r; if (row > M-1) row = M-1;
            int k = kbase + c4;
            cp16p(a_s + r*AS + c4, A + (size_t)row*K + k, (k < K) ? 16 : 0);
        }
        float* b_s = sB + buf*(BK*BS);
        #pragma unroll
        for (int i = 0; i < 4; i++){
            int idx = t + i*256;
            int r = idx >> 5, c4 = (idx & 31)*4;
            int kg = kbase + r;
            cp16p(b_s + r*BS + c4, B + (size_t)kg*Nn + colTile + c4, (kg < K) ? 16 : 0);
        }
        asm volatile("cp.async.commit_group;");
    };

    int lane = t & 31, warp = t >> 5;
    int wm = warp & 1, wn = warp >> 1;
    int gid = lane >> 2, tig = lane & 3;

    float acc[4][4][4];
    #pragma unroll
    for (int a = 0; a < 4; a++)
        #pragma unroll
        for (int b = 0; b < 4; b++)
            #pragma unroll
            for (int c = 0; c < 4; c++) acc[a][b][c] = 0.f;

    issue(0, 0);
    for (int kt = 0; kt < KT; kt++){
        if (kt + 1 < KT){
            issue(kt + 1, (kt + 1) & 1);
            asm volatile("cp.async.wait_group 1;");
        } else {
            asm volatile("cp.async.wait_group 0;");
        }
        __syncthreads();
        const float* a_s = sA + (kt & 1)*(BM*AS) + (wm*64)*AS;
        const float* b_s = sB + (kt & 1)*(BK*BS) + wn*32;
        #pragma unroll
        for (int ks = 0; ks < 4; ks++){
            int kb = ks*8;
            unsigned af[4][4], bf[4][2];
            #pragma unroll
            for (int mi = 0; mi < 4; mi++){
                const float* ap = a_s + (mi*16 + gid)*AS + kb + tig;
                af[mi][0] = f2tf(ap[0]);
                af[mi][1] = f2tf(ap[8*AS]);
                af[mi][2] = f2tf(ap[4]);
                af[mi][3] = f2tf(ap[8*AS + 4]);
            }
            #pragma unroll
            for (int ni = 0; ni < 4; ni++){
                const float* bp = b_s + (kb + tig)*BS + ni*8 + gid;
                bf[ni][0] = f2tf(bp[0]);
                bf[ni][1] = f2tf(bp[4*BS]);
            }
            #pragma unroll
            for (int mi = 0; mi < 4; mi++)
                #pragma unroll
                for (int ni = 0; ni < 4; ni++)
                    mma8(acc[mi][ni], af[mi], bf[ni]);
        }
        __syncthreads();
    }

    int rowBase = rowTile + wm*64;
    int colBase = colTile + wn*32;
    int b = rowBase / rowsPerGraph;
    #pragma unroll
    for (int ci = 0; ci < 8; ci++){
        int ni = ci >> 1;
        int col = colBase + ni*8 + tig*2 + (ci & 1);
        float m = -3.402823466e38f;
        #pragma unroll
        for (int ri = 0; ri < 8; ri++)
            m = fmaxf(m, acc[ri >> 1][ni][(ri & 1)*2 + (ci & 1)]);
        unsigned u = __float_as_uint(m);
        u = (u & 0x80000000u) ? ~u : (u | 0x80000000u);
        atomicMax(&g_maxenc[br][b*ND + col], u);
    }
}

// ------------------------- tails -------------------------
__global__ void k_fc(const float* __restrict__ W, const float* __restrict__ b, int br){
    int g = blockIdx.x, t = threadIdx.x;
    int c = g_bcnt[br][g]; if (c < 1) c = 1;
    float inv = 1.f / (float)c;
    const float* ps = &g_psum[br][g*NF];
    float acc = 0.f;
    #pragma unroll 8
    for (int k = 0; k < NF; k++) acc += ps[k] * W[k*ND + t];
    g_fcout[br][g*ND + t] = leaky(acc*inv + b[t]);
}

__global__ void k_final(const float* __restrict__ Wf, const float* __restrict__ bf,
                        const float* __restrict__ bm0, const float* __restrict__ bm1,
                        const float* __restrict__ bm2, const float* __restrict__ bm3,
                        float* __restrict__ out){
    __shared__ float sm[1024];
    int b = blockIdx.x, t = threadIdx.x;
    float contrib = 0.f;
    if (t < 768){
        int seg = t >> 7, o = t & 127;
        float val;
        if (seg == 0)      val = g_fcout[0][b*ND + o];
        else if (seg == 1) val = g_fcout[1][b*ND + o];
        else {
            int ci = seg - 2;
            unsigned u = g_maxenc[ci][b*ND + o];
            float dec = (u & 0x80000000u) ? __uint_as_float(u & 0x7FFFFFFFu)
                                          : __uint_as_float(~u);
            const float* bb = (ci == 0) ? bm0 : (ci == 1) ? bm1 : (ci == 2) ? bm2 : bm3;
            val = leaky(dec + bb[o]);
        }
        contrib = val * Wf[t];
    }
    sm[t] = contrib; __syncthreads();
    for (int s = 512; s > 0; s >>= 1){
        if (t < s) sm[t] += sm[t + s];
        __syncthreads();
    }
    if (t == 0) out[b] = sm[0] + bf[0];
}

// ------------------------- host -------------------------
extern "C" void kernel_launch(void* const* d_in, const int* in_sizes, int n_in,
                              void* d_out, int out_size){
    const float* pro_x[2]  = { (const float*)d_in[0], (const float*)d_in[3] };
    const int*   ei[2]     = { (const int*)d_in[1],   (const int*)d_in[4] };
    const int*   batch[2]  = { (const int*)d_in[2],   (const int*)d_in[5] };
    const float* mas[4]    = { (const float*)d_in[6], (const float*)d_in[7],
                               (const float*)d_in[8], (const float*)d_in[9] };
    const float* Wg[2]  = { (const float*)d_in[10], (const float*)d_in[14] };
    const float* bg[2]  = { (const float*)d_in[11], (const float*)d_in[15] };
    const float* Wfc[2] = { (const float*)d_in[12], (const float*)d_in[16] };
    const float* bfc[2] = { (const float*)d_in[13], (const float*)d_in[17] };
    const float* Wm[4]  = { (const float*)d_in[18], (const float*)d_in[20],
                            (const float*)d_in[22], (const float*)d_in[24] };
    const float* bm[4]  = { (const float*)d_in[19], (const float*)d_in[21],
                            (const float*)d_in[23], (const float*)d_in[25] };
    const float* Wfin = (const float*)d_in[26];
    const float* bfin = (const float*)d_in[27];
    float* out = (float*)d_out;

    void* aggPtr = nullptr; cudaGetSymbolAddress(&aggPtr, g_aggh);
    void* wtPtr  = nullptr; cudaGetSymbolAddress(&wtPtr, g_Wth);

    // one-time stream/event creation (objects only; no device memory)
    static cudaStream_t sBr0 = nullptr, sBr1 = nullptr, sCv = nullptr;
    static cudaEvent_t evInit = nullptr, ev0 = nullptr, ev1 = nullptr, ev2 = nullptr;
    if (!sBr0){
        cudaStreamCreateWithFlags(&sBr0, cudaStreamNonBlocking);
        cudaStreamCreateWithFlags(&sBr1, cudaStreamNonBlocking);
        cudaStreamCreateWithFlags(&sCv,  cudaStreamNonBlocking);
        cudaEventCreateWithFlags(&evInit, cudaEventDisableTiming);
        cudaEventCreateWithFlags(&ev0, cudaEventDisableTiming);
        cudaEventCreateWithFlags(&ev1, cudaEventDisableTiming);
        cudaEventCreateWithFlags(&ev2, cudaEventDisableTiming);
    }

    cudaFuncSetAttribute(k_gemm_max, cudaFuncAttributeMaxDynamicSharedMemorySize, SMEM_BYTES);
    cudaFuncSetAttribute(k_gcn,      cudaFuncAttributeMaxDynamicSharedMemorySize, FB_SMEM);

    k_init<<<(2*NNODES + 2*NB + 2*NB*NF + 4*NB*ND + 255)/256, 256>>>();
    cudaEventRecord(evInit, 0);

    cudaStream_t sb[2] = { sBr0, sBr1 };
    for (int br = 0; br < 2; br++){
        cudaStream_t s = sb[br];
        cudaStreamWaitEvent(s, evInit, 0);
        k_xcvt   <<<(NNODES*NF/4 + 255)/256, 256, 0, s>>>(pro_x[br], br);
        k_pre    <<<EBLK + NBLK + 1024, 256, 0, s>>>(ei[br], batch[br], Wg[br], br);
        k_scan   <<<1, 1024, 0, s>>>(br);
        k_scatter<<<EBLK, 256, 0, s>>>(ei[br], br);
        k_agg    <<<NNODES, 256, 0, s>>>(br);
        dim3 gfb(NF/BN, (NNODES + BM - 1)/BM);
        k_gcn<<<gfb, 256, FB_SMEM, s>>>((const __nv_bfloat16*)aggPtr + (size_t)br*NNODES*NF,
                                        (const __nv_bfloat16*)wtPtr + (size_t)br*NF*NF,
                                        bg[br], batch[br], NNODES, br);
        k_fc<<<NB, ND, 0, s>>>(Wfc[br], bfc[br], br);
    }
    cudaEventRecord(ev0, sBr0);
    cudaEventRecord(ev1, sBr1);

    cudaStreamWaitEvent(sCv, evInit, 0);
    for (int ci = 0; ci < 4; ci++){
        dim3 gc((NB*NL)/BM, 1);
        k_gemm_max<<<gc, 256, SMEM_BYTES, sCv>>>(mas[ci], Wm[ci], NB*NL, NDESC, ND, ci, NL);
    }
    cudaEventRecord(ev2, sCv);

    cudaStreamWaitEvent(0, ev0, 0);
    cudaStreamWaitEvent(0, ev1, 0);
    cudaStreamWaitEvent(0, ev2, 0);
    k_final<<<NB, 1024>>>(Wfin, bfin, bm[0], bm[1], bm[2], bm[3], out);
}